// round 1
// baseline (speedup 1.0000x reference)
#include <cuda_runtime.h>
#include <math.h>

#define H      64
#define NFINE  (1 << 20)          // fine grid intervals over [0,1]
#define NC     (1 << 14)          // coarse grid intervals (64x coarser)
#define NCTOT  (NC + 3)           // coarse entries: x = (idx-1)/NC, idx in [0, NC+2]
#define KBUCK  (1 << 22)          // inverse-index buckets over z in [0,1)
#define MONO   1e-3f

__device__ float g_w1[H], g_b1[H], g_w2[H * H], g_b2[H], g_w3[H], g_b3;
__device__ float g_Ac[NCTOT];         // raw A at coarse grid (with +/-1 pad)
__device__ float g_T[NFINE + 1];      // normalized F at fine grid
__device__ int   g_J[KBUCK];          // inverse bucket index: lower_bound(T, k/KBUCK)

__device__ __forceinline__ float sigmoidf(float x) {
    // stable for all ranges we see (args within [-10, 10])
    return 1.0f / (1.0f + expf(-x));
}

// ---------------------------------------------------------------------------
// Kernel 1: exponentiate the positivity-constrained weights once.
// ---------------------------------------------------------------------------
__global__ void prep_kernel(const float* __restrict__ pw1, const float* __restrict__ b1,
                            const float* __restrict__ pw2, const float* __restrict__ b2,
                            const float* __restrict__ pw3, const float* __restrict__ b3) {
    int i = blockIdx.x * blockDim.x + threadIdx.x;
    if (i < H * H) g_w2[i] = expf(pw2[i]);
    if (i < H) {
        g_w1[i] = expf(pw1[i]);
        g_b1[i] = b1[i];
        g_b2[i] = b2[i];
        g_w3[i] = expf(pw3[i]);
    }
    if (i == 0) g_b3 = b3[0];
}

// ---------------------------------------------------------------------------
// Kernel 2: exact network evaluation A(x) on the coarse grid (16387 points,
// including one pad point on each side for cubic interpolation).
// ---------------------------------------------------------------------------
__global__ void coarse_kernel() {
    __shared__ float sw2[H * H];
    __shared__ float sw1[H], sb1[H], sb2[H], sw3[H];
    int tid = threadIdx.x;
    for (int i = tid; i < H * H; i += blockDim.x) sw2[i] = g_w2[i];
    if (tid < H) {
        sw1[tid] = g_w1[tid];
        sb1[tid] = g_b1[tid];
        sb2[tid] = g_b2[tid];
        sw3[tid] = g_w3[tid];
    }
    __syncthreads();

    int idx = blockIdx.x * blockDim.x + tid;
    if (idx >= NCTOT) return;
    float x = (float)(idx - 1) * (1.0f / (float)NC);

    float h1[H];
#pragma unroll
    for (int i = 0; i < H; i++) h1[i] = sigmoidf(fmaf(sw1[i], x, sb1[i]));

    float y = g_b3;
#pragma unroll 4
    for (int j = 0; j < H; j++) {
        float acc = sb2[j];
#pragma unroll
        for (int i = 0; i < H; i++) acc = fmaf(sw2[j * H + i], h1[i], acc);
        y = fmaf(sigmoidf(acc), sw3[j], y);
    }
    g_Ac[idx] = sigmoidf(y) + MONO * x;
}

// ---------------------------------------------------------------------------
// Kernel 3: fill the fine grid T[j] = (A(j*2^-20) - A(0)) / (A(1) - A(0))
// via Catmull-Rom cubic through the coarse samples (error ~1e-15 << fp32 eps).
// Coarse points (f==0) take the exact coarse value.
// ---------------------------------------------------------------------------
__global__ void fine_kernel() {
    int j = blockIdx.x * blockDim.x + threadIdx.x;
    if (j > NFINE) return;
    const float a0 = g_Ac[1];        // A(0)
    const float a1 = g_Ac[1 + NC];   // A(1)
    int ci = j >> 6;
    int f  = j & 63;
    float A;
    if (f == 0) {
        A = __ldg(&g_Ac[ci + 1]);
    } else {
        float t  = (float)f * (1.0f / 64.0f);
        float P0 = __ldg(&g_Ac[ci]);
        float P1 = __ldg(&g_Ac[ci + 1]);
        float P2 = __ldg(&g_Ac[ci + 2]);
        float P3 = __ldg(&g_Ac[ci + 3]);
        float c1 = 0.5f * (P2 - P0);
        float c2 = P0 - 2.5f * P1 + 2.0f * P2 - 0.5f * P3;
        float c3 = 1.5f * (P1 - P2) + 0.5f * (P3 - P0);
        A = P1 + t * (c1 + t * (c2 + t * c3));
    }
    g_T[j] = (A - a0) / (a1 - a0);   // T[0] == 0.0f, T[NFINE] == 1.0f exactly
}

// ---------------------------------------------------------------------------
// Kernel 4: inverse bucket index. Thread j writes g_J[k] = j for all buckets
// k with T[j] <= k/KBUCK < T[j+1]. Runs are disjoint & together cover [0,K)
// (T[0]=0, T[NFINE]=1; power-of-2 scaling keeps ceil() arithmetic exact).
// ---------------------------------------------------------------------------
__global__ void jtab_kernel() {
    int j = blockIdx.x * blockDim.x + threadIdx.x;
    if (j >= NFINE) return;
    float t0 = g_T[j], t1 = g_T[j + 1];
    int k0 = (int)ceilf(t0 * (float)KBUCK);
    int k1 = (int)ceilf(t1 * (float)KBUCK);
    if (k0 < 0) k0 = 0;
    if (k1 > KBUCK) k1 = KBUCK;
    for (int k = k0; k < k1; k++) g_J[k] = j;
}

// ---------------------------------------------------------------------------
// Kernel 5: per-target inversion. Equivalent to the reference 20-step
// bisection: find j with T[j] <= z < T[j+1], return (j + 0.5) * 2^-20.
// Bucket lookup gives a bracket of average width 0.25, so the refine loop
// runs ~0-2 iterations.
// ---------------------------------------------------------------------------
__global__ void search_kernel(const float* __restrict__ z, float* __restrict__ out, int n) {
    int i = blockIdx.x * blockDim.x + threadIdx.x;
    if (i >= n) return;
    float zi = z[i];
    int k = (int)(zi * (float)KBUCK);        // exact: power-of-2 scale, truncation=floor
    if (k > KBUCK - 1) k = KBUCK - 1;
    if (k < 0) k = 0;
    int lo = __ldg(&g_J[k]);                             // T[lo] <= k/K <= zi
    int hi = (k == KBUCK - 1) ? NFINE : (__ldg(&g_J[k + 1]) + 1);  // T[hi] > (k+1)/K > zi
    while (hi - lo > 1) {
        int mid = (lo + hi) >> 1;
        float tv = __ldg(&g_T[mid]);
        if (tv <= zi) lo = mid; else hi = mid;
    }
    out[i] = (float)(2 * lo + 1) * 0x1p-21f;  // (lo + hi)/2 * 2^-20, exact
}

// ---------------------------------------------------------------------------
extern "C" void kernel_launch(void* const* d_in, const int* in_sizes, int n_in,
                              void* d_out, int out_size) {
    const float* z   = (const float*)d_in[0];
    const float* pw1 = (const float*)d_in[1];
    const float* b1  = (const float*)d_in[2];
    const float* pw2 = (const float*)d_in[3];
    const float* b2  = (const float*)d_in[4];
    const float* pw3 = (const float*)d_in[5];
    const float* b3  = (const float*)d_in[6];
    float* out = (float*)d_out;
    int n = in_sizes[0];

    prep_kernel<<<(H * H + 255) / 256, 256>>>(pw1, b1, pw2, b2, pw3, b3);
    coarse_kernel<<<(NCTOT + 127) / 128, 128>>>();
    fine_kernel<<<(NFINE + 1 + 255) / 256, 256>>>();
    jtab_kernel<<<(NFINE + 255) / 256, 256>>>();
    search_kernel<<<(n + 255) / 256, 256>>>(z, out, n);
}

// round 2
// speedup vs baseline: 1.2410x; 1.2410x over previous
#include <cuda_runtime.h>
#include <math.h>

#define H      64
#define NFINE  (1 << 20)          // fine grid intervals over [0,1]
#define NC     (1 << 14)          // coarse grid intervals (64x coarser)
#define NCTOT  (NC + 3)           // coarse entries: x = (idx-1)/NC, idx in [0, NC+2]
#define KBUCK  (1 << 20)          // inverse-index buckets over z in [0,1)  (== NFINE)
#define MONO   1e-3f

__device__ float g_Ac[NCTOT];         // raw A at coarse grid (with +/-1 pad)
__device__ float g_T[NFINE + 1];      // normalized F at fine grid
__device__ int   g_J[KBUCK];          // inverse bucket index: lower_bound(T, k/KBUCK)

__device__ __forceinline__ float sigmoidf(float x) {
    return 1.0f / (1.0f + expf(-x));
}

// ---------------------------------------------------------------------------
// Kernel 1: exact network evaluation A(x) on the coarse grid. Each block
// exponentiates the positivity-constrained weights into smem itself (4K expf
// per block is negligible) -- no separate prep kernel / global round-trip.
// ---------------------------------------------------------------------------
__global__ void coarse_kernel(const float* __restrict__ pw1, const float* __restrict__ b1,
                              const float* __restrict__ pw2, const float* __restrict__ b2,
                              const float* __restrict__ pw3, const float* __restrict__ b3) {
    __shared__ float sw2[H * H];
    __shared__ float sw1[H], sb1[H], sb2[H], sw3[H];
    __shared__ float sb3;
    int tid = threadIdx.x;
    for (int i = tid; i < H * H; i += blockDim.x) sw2[i] = expf(pw2[i]);
    if (tid < H) {
        sw1[tid] = expf(pw1[tid]);
        sb1[tid] = b1[tid];
        sb2[tid] = b2[tid];
        sw3[tid] = expf(pw3[tid]);
    }
    if (tid == 0) sb3 = b3[0];
    __syncthreads();

    int idx = blockIdx.x * blockDim.x + tid;
    if (idx >= NCTOT) return;
    float x = (float)(idx - 1) * (1.0f / (float)NC);

    float h1[H];
#pragma unroll
    for (int i = 0; i < H; i++) h1[i] = sigmoidf(fmaf(sw1[i], x, sb1[i]));

    float y = sb3;
#pragma unroll 4
    for (int j = 0; j < H; j++) {
        float acc = sb2[j];
#pragma unroll
        for (int i = 0; i < H; i++) acc = fmaf(sw2[j * H + i], h1[i], acc);
        y = fmaf(sigmoidf(acc), sw3[j], y);
    }
    g_Ac[idx] = sigmoidf(y) + MONO * x;
}

// ---------------------------------------------------------------------------
// Catmull-Rom interpolation of A at fine index jj (error ~1e-15 vs exact,
// far below fp32 rounding of A itself). Coarse points take the exact value.
// ---------------------------------------------------------------------------
__device__ __forceinline__ float eval_A(int jj) {
    int ci = jj >> 6;
    int f  = jj & 63;
    if (f == 0) return __ldg(&g_Ac[ci + 1]);
    float t  = (float)f * (1.0f / 64.0f);
    float P0 = __ldg(&g_Ac[ci]);
    float P1 = __ldg(&g_Ac[ci + 1]);
    float P2 = __ldg(&g_Ac[ci + 2]);
    float P3 = __ldg(&g_Ac[ci + 3]);
    float c1 = 0.5f * (P2 - P0);
    float c2 = P0 - 2.5f * P1 + 2.0f * P2 - 0.5f * P3;
    float c3 = 1.5f * (P1 - P2) + 0.5f * (P3 - P0);
    return P1 + t * (c1 + t * (c2 + t * c3));
}

// ---------------------------------------------------------------------------
// Kernel 2 (fused fine+jtab): thread j computes T[j] and T[j+1] inline
// (coarse table is L1/L2 resident), writes T[j], and writes its inverse
// bucket run g_J[k] = j for k in [ceil(T[j]*K), ceil(T[j+1]*K)).
// Power-of-2 scaling keeps all ceil()/floor() arithmetic exact, so the runs
// are disjoint and cover [0, K).
// ---------------------------------------------------------------------------
__global__ void table_kernel() {
    int j = blockIdx.x * blockDim.x + threadIdx.x;
    if (j >= NFINE) return;
    const float a0  = g_Ac[1];        // A(0)
    const float a1  = g_Ac[1 + NC];   // A(1)
    const float den = a1 - a0;

    float t0 = (eval_A(j) - a0) / den;       // T[0] == 0.0f exactly
    float t1 = (eval_A(j + 1) - a0) / den;   // T[NFINE] == 1.0f exactly

    g_T[j] = t0;
    if (j == NFINE - 1) g_T[NFINE] = t1;

    int k0 = (int)ceilf(t0 * (float)KBUCK);
    int k1 = (int)ceilf(t1 * (float)KBUCK);
    if (k0 < 0) k0 = 0;
    if (k1 > KBUCK) k1 = KBUCK;
    for (int k = k0; k < k1; k++) g_J[k] = j;
}

// ---------------------------------------------------------------------------
// Kernel 3: per-target inversion, 4 targets per thread for MLP.
// Equivalent to the reference 20-step bisection: find j with
// T[j] <= z < T[j+1], return (j + 0.5) * 2^-20.
// ---------------------------------------------------------------------------
__device__ __forceinline__ float invert_one(float zi) {
    int k = (int)(zi * (float)KBUCK);        // exact: power-of-2 scale
    if (k > KBUCK - 1) k = KBUCK - 1;
    if (k < 0) k = 0;
    int lo = __ldg(&g_J[k]);                                 // T[lo] <= k/K <= zi
    int hi = (k == KBUCK - 1) ? NFINE : (__ldg(&g_J[k + 1]) + 1);  // T[hi] > zi
    while (hi - lo > 1) {
        int mid = (lo + hi) >> 1;
        if (__ldg(&g_T[mid]) <= zi) lo = mid; else hi = mid;
    }
    return (float)(2 * lo + 1) * 0x1p-21f;   // (lo + hi)/2 * 2^-20, exact
}

__global__ void search_kernel(const float* __restrict__ z, float* __restrict__ out, int n) {
    int i = (blockIdx.x * blockDim.x + threadIdx.x) * 4;
    if (i + 3 < n) {
        float4 zv = *reinterpret_cast<const float4*>(z + i);
        float4 ov;
        ov.x = invert_one(zv.x);
        ov.y = invert_one(zv.y);
        ov.z = invert_one(zv.z);
        ov.w = invert_one(zv.w);
        *reinterpret_cast<float4*>(out + i) = ov;
    } else {
        for (; i < n; i++) out[i] = invert_one(z[i]);
    }
}

// ---------------------------------------------------------------------------
extern "C" void kernel_launch(void* const* d_in, const int* in_sizes, int n_in,
                              void* d_out, int out_size) {
    const float* z   = (const float*)d_in[0];
    const float* pw1 = (const float*)d_in[1];
    const float* b1  = (const float*)d_in[2];
    const float* pw2 = (const float*)d_in[3];
    const float* b2  = (const float*)d_in[4];
    const float* pw3 = (const float*)d_in[5];
    const float* b3  = (const float*)d_in[6];
    float* out = (float*)d_out;
    int n = in_sizes[0];

    coarse_kernel<<<(NCTOT + 127) / 128, 128>>>(pw1, b1, pw2, b2, pw3, b3);
    table_kernel<<<(NFINE + 255) / 256, 256>>>();
    int nq = (n + 3) / 4;
    search_kernel<<<(nq + 255) / 256, 256>>>(z, out, n);
}

// round 3
// speedup vs baseline: 1.7552x; 1.4143x over previous
#include <cuda_runtime.h>
#include <math.h>

#define H      64
#define NFINE  (1 << 20)          // fine grid intervals over [0,1]
#define NC     (1 << 12)          // coarse grid intervals (256x coarser)
#define NCTOT  (NC + 3)           // coarse entries: x = (idx-1)/NC
#define RATIO  256                // NFINE / NC
#define KBUCK  (1 << 20)          // inverse-index buckets over z in [0,1)
#define MONO   1e-3f

__device__ float g_Ac[NCTOT];                        // raw A at coarse grid (+/-1 pad)
__device__ __align__(16) float g_T[NFINE + 1];       // normalized F at fine grid
__device__ unsigned long long g_C[KBUCK];            // packed {J[k] : hi32, T[J[k]+1] : lo32}

__device__ __forceinline__ float sigmoidf(float x) {
    return 1.0f / (1.0f + expf(-x));
}

// ---------------------------------------------------------------------------
// Kernel 1: exact network eval A(x) on the coarse grid, ONE WARP PER POINT.
// Lane l computes h1[l], h1[l+32] (layer 1) and owns output neurons 2l, 2l+1.
// h1 values are broadcast across the warp with shuffles; w2 sits exp'd +
// TRANSPOSED (+pad 66) in smem so each lane reads a conflict-free float2.
// ---------------------------------------------------------------------------
__global__ void coarse_kernel(const float* __restrict__ pw1, const float* __restrict__ b1,
                              const float* __restrict__ pw2, const float* __restrict__ b2,
                              const float* __restrict__ pw3, const float* __restrict__ b3) {
    __shared__ float sw2t[H * 66];                 // sw2t[i*66 + j] = exp(w2[j][i])
    __shared__ float sw1[H], sb1[H], sb2[H], sw3[H];
    __shared__ float sb3;
    int tid = threadIdx.x;
    for (int e = tid; e < H * H; e += 256) {
        int j = e >> 6, i = e & 63;                // pw2 row-major [j][i], coalesced read
        sw2t[i * 66 + j] = expf(pw2[e]);           // stride-66 write: conflict-free
    }
    if (tid < H) {
        sw1[tid] = expf(pw1[tid]);
        sb1[tid] = b1[tid];
        sb2[tid] = b2[tid];
        sw3[tid] = expf(pw3[tid]);
    }
    if (tid == 0) sb3 = b3[0];
    __syncthreads();

    int gwarp = (blockIdx.x * blockDim.x + tid) >> 5;
    int lane  = tid & 31;
    if (gwarp >= NCTOT) return;
    float x = (float)(gwarp - 1) * (1.0f / (float)NC);

    float h1a = sigmoidf(fmaf(sw1[lane],      x, sb1[lane]));
    float h1b = sigmoidf(fmaf(sw1[lane + 32], x, sb1[lane + 32]));

    float acc0 = sb2[2 * lane];
    float acc1 = sb2[2 * lane + 1];
#pragma unroll
    for (int i = 0; i < 32; i++) {
        float  hv = __shfl_sync(0xffffffffu, h1a, i);
        float2 w  = *reinterpret_cast<const float2*>(&sw2t[i * 66 + 2 * lane]);
        acc0 = fmaf(w.x, hv, acc0);
        acc1 = fmaf(w.y, hv, acc1);
    }
#pragma unroll
    for (int i = 0; i < 32; i++) {
        float  hv = __shfl_sync(0xffffffffu, h1b, i);
        float2 w  = *reinterpret_cast<const float2*>(&sw2t[(i + 32) * 66 + 2 * lane]);
        acc0 = fmaf(w.x, hv, acc0);
        acc1 = fmaf(w.y, hv, acc1);
    }
    float part = fmaf(sigmoidf(acc0), sw3[2 * lane], sigmoidf(acc1) * sw3[2 * lane + 1]);
#pragma unroll
    for (int o = 16; o; o >>= 1) part += __shfl_xor_sync(0xffffffffu, part, o);

    if (lane == 0) g_Ac[gwarp] = sigmoidf(part + sb3) + MONO * x;
}

// ---------------------------------------------------------------------------
// Catmull-Rom interpolation of A at fine index j (error ~1e-14 vs exact,
// far below fp32 rounding of A itself). Coarse points take the exact value.
// ---------------------------------------------------------------------------
__device__ __forceinline__ float evalA(int j) {
    int ci = j >> 8;
    int f  = j & 255;
    if (f == 0) return __ldg(&g_Ac[ci + 1]);
    float t  = (float)f * (1.0f / 256.0f);
    float P0 = __ldg(&g_Ac[ci]);
    float P1 = __ldg(&g_Ac[ci + 1]);
    float P2 = __ldg(&g_Ac[ci + 2]);
    float P3 = __ldg(&g_Ac[ci + 3]);
    float c1 = 0.5f * (P2 - P0);
    float c2 = P0 - 2.5f * P1 + 2.0f * P2 - 0.5f * P3;
    float c3 = 1.5f * (P1 - P2) + 0.5f * (P3 - P0);
    return P1 + t * (c1 + t * (c2 + t * c3));
}

// ---------------------------------------------------------------------------
// Kernel 2: fused fine-table + packed inverse index. Thread handles 4 fine
// points: evaluates T at j..j+4 (shared endpoints use identical arithmetic in
// every thread, so bucket runs tile exactly), float4-stores T, and writes
// g_C[k] = {j, T[j+1]} for k in [ceil(T[j]*K), ceil(T[j+1]*K)).
// ---------------------------------------------------------------------------
__global__ void table_kernel() {
    int jb = (blockIdx.x * blockDim.x + threadIdx.x) * 4;
    if (jb >= NFINE) return;
    const float a0      = g_Ac[1];        // A(0)
    const float a1      = g_Ac[1 + NC];   // A(1)
    const float inv_den = 1.0f / (a1 - a0);

    float tv[5];
#pragma unroll
    for (int m = 0; m < 5; m++) {
        int j = jb + m;
        float v = (evalA(j) - a0) * inv_den;      // j==0 -> exactly 0.0f
        tv[m] = (j == NFINE) ? 1.0f : v;          // pin top to 1.0f (coverage)
    }
    *reinterpret_cast<float4*>(&g_T[jb]) = make_float4(tv[0], tv[1], tv[2], tv[3]);
    if (jb + 4 == NFINE) g_T[NFINE] = 1.0f;

#pragma unroll
    for (int m = 0; m < 4; m++) {
        int k0 = (int)ceilf(tv[m]     * (float)KBUCK);   // exact: pow2 scale
        int k1 = (int)ceilf(tv[m + 1] * (float)KBUCK);
        if (k0 < 0) k0 = 0;
        if (k1 > KBUCK) k1 = KBUCK;
        unsigned long long val =
            ((unsigned long long)(unsigned)(jb + m) << 32) |
            (unsigned long long)__float_as_uint(tv[m + 1]);
        for (int k = k0; k < k1; k++) g_C[k] = val;
    }
}

// ---------------------------------------------------------------------------
// Kernel 3: per-target inversion, 4 targets/thread. Two adjacent 8B C-loads
// give lo, hi AND T[lo+1], resolving brackets of width <= 2 (the common case)
// with no T gather; wider brackets fall back to bisection on g_T.
// Equivalent to the reference 20-step bisection.
// ---------------------------------------------------------------------------
__device__ __forceinline__ float invert_one(float zi) {
    int k = (int)(zi * (float)KBUCK);            // exact floor: pow2 scale
    k = min(max(k, 0), KBUCK - 1);
    unsigned long long c0 = __ldg(&g_C[k]);
    int   lo = (int)(c0 >> 32);                  // T[lo] <= k/K <= zi
    float tn = __uint_as_float((unsigned)c0);    // T[lo+1]
    int hi = (k < KBUCK - 1) ? ((int)(__ldg(&g_C[k + 1]) >> 32) + 1) : NFINE;
    // T[hi] > zi
    if (hi - lo > 1) {
        if (tn <= zi) lo += 1; else hi = lo + 1;
        while (hi - lo > 1) {
            int mid = (lo + hi) >> 1;
            if (__ldg(&g_T[mid]) <= zi) lo = mid; else hi = mid;
        }
    }
    return (float)(2 * lo + 1) * 0x1p-21f;       // (lo + hi)/2 * 2^-20, exact
}

__global__ void search_kernel(const float* __restrict__ z, float* __restrict__ out, int n) {
    int i = (blockIdx.x * blockDim.x + threadIdx.x) * 4;
    if (i + 3 < n) {
        float4 zv = *reinterpret_cast<const float4*>(z + i);
        float4 ov;
        ov.x = invert_one(zv.x);
        ov.y = invert_one(zv.y);
        ov.z = invert_one(zv.z);
        ov.w = invert_one(zv.w);
        *reinterpret_cast<float4*>(out + i) = ov;
    } else {
        for (; i < n; i++) out[i] = invert_one(z[i]);
    }
}

// ---------------------------------------------------------------------------
extern "C" void kernel_launch(void* const* d_in, const int* in_sizes, int n_in,
                              void* d_out, int out_size) {
    const float* z   = (const float*)d_in[0];
    const float* pw1 = (const float*)d_in[1];
    const float* b1  = (const float*)d_in[2];
    const float* pw2 = (const float*)d_in[3];
    const float* b2  = (const float*)d_in[4];
    const float* pw3 = (const float*)d_in[5];
    const float* b3  = (const float*)d_in[6];
    float* out = (float*)d_out;
    int n = in_sizes[0];

    coarse_kernel<<<(NCTOT * 32 + 255) / 256, 256>>>(pw1, b1, pw2, b2, pw3, b3);
    table_kernel<<<(NFINE / 4 + 255) / 256, 256>>>();
    int nq = (n + 3) / 4;
    search_kernel<<<(nq + 255) / 256, 256>>>(z, out, n);
}